// round 7
// baseline (speedup 1.0000x reference)
#include <cuda_runtime.h>

#define MB 32
#define NP 256
#define QP (NP / 2)
#define ND 512
#define NBLK (MB * MB + MB)

// scratch (no allocations allowed)
__device__ float g_D[MB * MB];      // D(i,j) = mean_p min_q d2
__device__ float g_dot[MB * MB];    // normalized inner products
__device__ int   g_counter;         // zero-init; reset by finale each run

// ---- packed f32x2 helpers (Blackwell FFMA2 path) ---------------------------
__device__ __forceinline__ unsigned long long pack2(float lo, float hi) {
    unsigned long long r;
    asm("mov.b64 %0, {%1, %2};" : "=l"(r) : "f"(lo), "f"(hi));
    return r;
}
__device__ __forceinline__ unsigned long long fma2(unsigned long long a,
                                                   unsigned long long b,
                                                   unsigned long long c) {
    unsigned long long d;
    asm("fma.rn.f32x2 %0, %1, %2, %3;" : "=l"(d) : "l"(a), "l"(b), "l"(c));
    return d;
}
__device__ __forceinline__ void unpack2(unsigned long long v, float& lo, float& hi) {
    asm("mov.b64 {%0, %1}, %2;" : "=f"(lo), "=f"(hi) : "l"(v));
}

// ---------------------------------------------------------------------------
// Single fused kernel, 1056 blocks x 128 threads:
//   blocks [0,1024): chamfer D(i,j), ordered pair (i = b>>5, j = b&31)
//   blocks [1024,1056): normalized inner_dot row (i = b-1024)
// Last block to finish (atomic ticket) runs the softmax finale and writes out.
// ---------------------------------------------------------------------------
__global__ void fused_kernel(const float* __restrict__ xyz,
                             const float* __restrict__ emb,
                             float* __restrict__ out) {
    const int b = blockIdx.x;
    const int t = threadIdx.x;          // 0..127
    const int w = t >> 5, lane = t & 31;

    __shared__ float4 s_j[2 * QP];
    __shared__ float  s_red[4];
    __shared__ int    s_last;
    __shared__ float  s_row[MB];

    if (b < MB * MB) {
        // ---------------- chamfer part ----------------
        const int i = b >> 5, j = b & 31;
        const float* shapes = xyz + MB * NP * 3;

        // stage shape j pair-interleaved SoA: {x0,x1,y0,y1} | {z0,z1,w0,w1}
        for (int q = t; q < NP; q += 128) {
            const float* p = shapes + (j * NP + q) * 3;
            float x = p[0], y = p[1], z = p[2];
            float ww = x * x + y * y + z * z;
            float* base = reinterpret_cast<float*>(&s_j[(q >> 1) * 2]);
            int s = q & 1;
            base[0 + s] = x;
            base[2 + s] = y;
            base[4 + s] = z;
            base[6 + s] = ww;
        }

        // my 2 a-points, pre-scaled by -2, splatted to f32x2
        unsigned long long a2x[2], a2y[2], a2z[2];
        float aw[2];
#pragma unroll
        for (int k = 0; k < 2; k++) {
            const float* p = shapes + (i * NP + t + 128 * k) * 3;
            float x = p[0], y = p[1], z = p[2];
            aw[k] = x * x + y * y + z * z;
            a2x[k] = pack2(-2.f * x, -2.f * x);
            a2y[k] = pack2(-2.f * y, -2.f * y);
            a2z[k] = pack2(-2.f * z, -2.f * z);
        }

        __syncthreads();

        const float INF = 3.4e38f;
        float mlo[2] = {INF, INF};
        float mhi[2] = {INF, INF};

        const ulonglong2* sj64 = reinterpret_cast<const ulonglong2*>(s_j);

#pragma unroll 8
        for (int qp = 0; qp < QP; qp++) {
            ulonglong2 xy = sj64[2 * qp + 0];  // {x01, y01}
            ulonglong2 zw = sj64[2 * qp + 1];  // {z01, w01}
#pragma unroll
            for (int k = 0; k < 2; k++) {
                unsigned long long s =
                    fma2(a2x[k], xy.x, fma2(a2y[k], xy.y, fma2(a2z[k], zw.x, zw.y)));
                float lo, hi;
                unpack2(s, lo, hi);
                mlo[k] = fminf(mlo[k], lo);
                mhi[k] = fminf(mhi[k], hi);
            }
        }

        float s = fminf(mlo[0], mhi[0]) + aw[0] + fminf(mlo[1], mhi[1]) + aw[1];
#pragma unroll
        for (int o = 16; o > 0; o >>= 1) s += __shfl_down_sync(0xffffffffu, s, o);
        if (lane == 0) s_red[w] = s;
        __syncthreads();
        if (t == 0)
            g_D[i * MB + j] = (s_red[0] + s_red[1] + s_red[2] + s_red[3]) * (1.f / NP);
    } else {
        // ---------------- inner_dot row part ----------------
        const int i = b - MB * MB;

        // keep my slice of emb row i in registers, reuse for all j
        float eir[16];
        float ni = 0.f;
#pragma unroll
        for (int u = 0; u < 16; u++) {
            float e = emb[i * ND + u * 32 + lane];
            eir[u] = e;
            ni += e * e;
        }
#pragma unroll
        for (int o = 16; o > 0; o >>= 1) ni += __shfl_xor_sync(0xffffffffu, ni, o);
        const float inv_ni = rsqrtf(ni);

        for (int j = w; j < MB; j += 4) {
            const float* ej = emb + (MB + j) * ND;
            float dot = 0.f, nj = 0.f;
#pragma unroll
            for (int u = 0; u < 16; u++) {
                float e = ej[u * 32 + lane];
                dot += e * eir[u];
                nj += e * e;
            }
#pragma unroll
            for (int o = 16; o > 0; o >>= 1) {
                dot += __shfl_down_sync(0xffffffffu, dot, o);
                nj  += __shfl_down_sync(0xffffffffu, nj, o);
            }
            if (lane == 0) g_dot[i * MB + j] = dot * rsqrtf(nj) * inv_ni;
        }
    }

    // ---------------- ticket: last block runs the finale ----------------
    __syncthreads();
    if (t == 0) {
        __threadfence();
        int ticket = atomicAdd(&g_counter, 1);
        s_last = (ticket == NBLK - 1) ? 1 : 0;
    }
    __syncthreads();
    if (!s_last) return;

    __threadfence();  // acquire: observe all g_D / g_dot writes

    // 4 warps x 8 rows each: softmaxes + row |diff| sums
    const float SIG = 1.0f * 0.997f / 3.0f;
    const float INV2S2 = 1.0f / (2.0f * SIG * SIG);
#pragma unroll
    for (int r = 0; r < 8; r++) {
        const int i = w * 8 + r;

        float idot = g_dot[i * MB + lane];
        float m = idot;
#pragma unroll
        for (int o = 16; o > 0; o >>= 1) m = fmaxf(m, __shfl_xor_sync(0xffffffffu, m, o));
        float e = expf(idot - m);
        float sum = e;
#pragma unroll
        for (int o = 16; o > 0; o >>= 1) sum += __shfl_xor_sync(0xffffffffu, sum, o);
        float p_hat = e / sum;

        float cd = g_D[i * MB + lane] + g_D[lane * MB + i];
        float nd = -(cd * cd) * INV2S2;
        float m2 = nd;
#pragma unroll
        for (int o = 16; o > 0; o >>= 1) m2 = fmaxf(m2, __shfl_xor_sync(0xffffffffu, m2, o));
        float e2 = expf(nd - m2);
        float sum2 = e2;
#pragma unroll
        for (int o = 16; o > 0; o >>= 1) sum2 += __shfl_xor_sync(0xffffffffu, sum2, o);
        float p = e2 / sum2;

        float diff = fabsf(p_hat - p);
#pragma unroll
        for (int o = 16; o > 0; o >>= 1) diff += __shfl_xor_sync(0xffffffffu, diff, o);
        if (lane == 0) s_row[i] = diff;
    }
    __syncthreads();

    if (w == 0) {
        float v = s_row[lane];
#pragma unroll
        for (int o = 16; o > 0; o >>= 1) v += __shfl_down_sync(0xffffffffu, v, o);
        if (lane == 0) {
            out[0] = v * (1.0f / (MB * MB));
            g_counter = 0;  // reset for next graph replay
        }
    }
}

extern "C" void kernel_launch(void* const* d_in, const int* in_sizes, int n_in,
                              void* d_out, int out_size) {
    const float* embeddings = (const float*)d_in[0];  // (64, 512) fp32
    const float* xyz        = (const float*)d_in[1];  // (64, 256, 3) fp32
    float* out = (float*)d_out;

    fused_kernel<<<NBLK, 128>>>(xyz, embeddings, out);
}

// round 8
// speedup vs baseline: 1.2021x; 1.2021x over previous
#include <cuda_runtime.h>

#define MB 32
#define NP 256
#define QP (NP / 2)
#define ND 512

// scratch (no allocations allowed)
__device__ float g_D[MB * MB];      // D(i,j) = mean_p min_q d2
__device__ float g_dot[MB * MB];    // normalized inner products

// ---- packed f32x2 helpers (Blackwell FFMA2 path) ---------------------------
__device__ __forceinline__ unsigned long long pack2(float lo, float hi) {
    unsigned long long r;
    asm("mov.b64 %0, {%1, %2};" : "=l"(r) : "f"(lo), "f"(hi));
    return r;
}
__device__ __forceinline__ unsigned long long fma2(unsigned long long a,
                                                   unsigned long long b,
                                                   unsigned long long c) {
    unsigned long long d;
    asm("fma.rn.f32x2 %0, %1, %2, %3;" : "=l"(d) : "l"(a), "l"(b), "l"(c));
    return d;
}
__device__ __forceinline__ void unpack2(unsigned long long v, float& lo, float& hi) {
    asm("mov.b64 {%0, %1}, %2;" : "=f"(lo), "=f"(hi) : "l"(v));
}

// ---------------------------------------------------------------------------
// Kernel A, flat grid of 1056 blocks x 128 threads:
//   blocks [0,1024): chamfer D(i,j) for ordered pair (i = b>>5, j = b&31)
//   blocks [1024,1056): normalized inner_dot row (i = b-1024)
// ---------------------------------------------------------------------------
__global__ void fused_A_kernel(const float* __restrict__ xyz,
                               const float* __restrict__ emb) {
    const int b = blockIdx.x;
    const int t = threadIdx.x;          // 0..127
    const int w = t >> 5, lane = t & 31;

    if (b < MB * MB) {
        // ---------------- chamfer part ----------------
        const int i = b >> 5, j = b & 31;
        __shared__ float4 s_j[2 * QP];
        __shared__ float  s_red[4];

        const float* shapes = xyz + MB * NP * 3;

        // stage shape j pair-interleaved SoA: {x0,x1,y0,y1} | {z0,z1,w0,w1}
        for (int q = t; q < NP; q += 128) {
            const float* p = shapes + (j * NP + q) * 3;
            float x = p[0], y = p[1], z = p[2];
            float ww = x * x + y * y + z * z;
            float* base = reinterpret_cast<float*>(&s_j[(q >> 1) * 2]);
            int s = q & 1;
            base[0 + s] = x;
            base[2 + s] = y;
            base[4 + s] = z;
            base[6 + s] = ww;
        }

        // my 2 a-points, pre-scaled by -2, splatted to f32x2
        unsigned long long a2x[2], a2y[2], a2z[2];
        float aw[2];
#pragma unroll
        for (int k = 0; k < 2; k++) {
            const float* p = shapes + (i * NP + t + 128 * k) * 3;
            float x = p[0], y = p[1], z = p[2];
            aw[k] = x * x + y * y + z * z;
            a2x[k] = pack2(-2.f * x, -2.f * x);
            a2y[k] = pack2(-2.f * y, -2.f * y);
            a2z[k] = pack2(-2.f * z, -2.f * z);
        }

        __syncthreads();

        const float INF = 3.4e38f;
        float mlo[2] = {INF, INF};
        float mhi[2] = {INF, INF};

        const ulonglong2* sj64 = reinterpret_cast<const ulonglong2*>(s_j);

#pragma unroll 4
        for (int qp = 0; qp < QP; qp++) {
            ulonglong2 xy = sj64[2 * qp + 0];  // {x01, y01}
            ulonglong2 zw = sj64[2 * qp + 1];  // {z01, w01}
#pragma unroll
            for (int k = 0; k < 2; k++) {
                unsigned long long s =
                    fma2(a2x[k], xy.x, fma2(a2y[k], xy.y, fma2(a2z[k], zw.x, zw.y)));
                float lo, hi;
                unpack2(s, lo, hi);
                mlo[k] = fminf(mlo[k], lo);
                mhi[k] = fminf(mhi[k], hi);
            }
        }

        float s = fminf(mlo[0], mhi[0]) + aw[0] + fminf(mlo[1], mhi[1]) + aw[1];
#pragma unroll
        for (int o = 16; o > 0; o >>= 1) s += __shfl_down_sync(0xffffffffu, s, o);
        if (lane == 0) s_red[w] = s;
        __syncthreads();
        if (t == 0)
            g_D[i * MB + j] = (s_red[0] + s_red[1] + s_red[2] + s_red[3]) * (1.f / NP);
    } else {
        // ---------------- inner_dot row part ----------------
        const int i = b - MB * MB;

        // keep my slice of emb row i in registers, reuse for all j
        float eir[16];
        float ni = 0.f;
#pragma unroll
        for (int u = 0; u < 16; u++) {
            float e = emb[i * ND + u * 32 + lane];
            eir[u] = e;
            ni += e * e;
        }
#pragma unroll
        for (int o = 16; o > 0; o >>= 1) ni += __shfl_xor_sync(0xffffffffu, ni, o);
        const float inv_ni = rsqrtf(ni);

        for (int j = w; j < MB; j += 4) {
            const float* ej = emb + (MB + j) * ND;
            float dot = 0.f, nj = 0.f;
#pragma unroll
            for (int u = 0; u < 16; u++) {
                float e = ej[u * 32 + lane];
                dot += e * eir[u];
                nj += e * e;
            }
#pragma unroll
            for (int o = 16; o > 0; o >>= 1) {
                dot += __shfl_down_sync(0xffffffffu, dot, o);
                nj  += __shfl_down_sync(0xffffffffu, nj, o);
            }
            if (lane == 0) g_dot[i * MB + j] = dot * rsqrtf(nj) * inv_ni;
        }
    }
}

// ---------------------------------------------------------------------------
// Kernel B: 1 block x 1024 threads, launched with PDL so its launch latency
// overlaps kernel A's tail. Warp i handles row i; warp 0 does the final sum.
// ---------------------------------------------------------------------------
__global__ void final_B_kernel(float* __restrict__ out) {
    // PDL: wait for the upstream grid (fused_A) to fully complete before
    // reading g_D / g_dot.
    cudaGridDependencySynchronize();

    __shared__ float s_row[MB];
    const int i = threadIdx.x >> 5, lane = threadIdx.x & 31;

    {
        float idot = g_dot[i * MB + lane];
        float m = idot;
#pragma unroll
        for (int o = 16; o > 0; o >>= 1) m = fmaxf(m, __shfl_xor_sync(0xffffffffu, m, o));
        float e = expf(idot - m);
        float sum = e;
#pragma unroll
        for (int o = 16; o > 0; o >>= 1) sum += __shfl_xor_sync(0xffffffffu, sum, o);
        float p_hat = e / sum;

        const float SIG = 1.0f * 0.997f / 3.0f;
        const float INV2S2 = 1.0f / (2.0f * SIG * SIG);
        float cd = g_D[i * MB + lane] + g_D[lane * MB + i];
        float nd = -(cd * cd) * INV2S2;
        float m2 = nd;
#pragma unroll
        for (int o = 16; o > 0; o >>= 1) m2 = fmaxf(m2, __shfl_xor_sync(0xffffffffu, m2, o));
        float e2 = expf(nd - m2);
        float sum2 = e2;
#pragma unroll
        for (int o = 16; o > 0; o >>= 1) sum2 += __shfl_xor_sync(0xffffffffu, sum2, o);
        float p = e2 / sum2;

        float diff = fabsf(p_hat - p);
#pragma unroll
        for (int o = 16; o > 0; o >>= 1) diff += __shfl_xor_sync(0xffffffffu, diff, o);
        if (lane == 0) s_row[i] = diff;
    }
    __syncthreads();

    if (i == 0) {
        float v = s_row[lane];
#pragma unroll
        for (int o = 16; o > 0; o >>= 1) v += __shfl_down_sync(0xffffffffu, v, o);
        if (lane == 0) out[0] = v * (1.0f / (MB * MB));
    }
}

extern "C" void kernel_launch(void* const* d_in, const int* in_sizes, int n_in,
                              void* d_out, int out_size) {
    const float* embeddings = (const float*)d_in[0];  // (64, 512) fp32
    const float* xyz        = (const float*)d_in[1];  // (64, 256, 3) fp32
    float* out = (float*)d_out;

    fused_A_kernel<<<MB * MB + MB, 128>>>(xyz, embeddings);

    // PDL launch of the epilogue: overlaps its launch latency with A's tail.
    cudaLaunchConfig_t cfg = {};
    cfg.gridDim  = dim3(1, 1, 1);
    cfg.blockDim = dim3(MB * 32, 1, 1);
    cfg.dynamicSmemBytes = 0;
    cfg.stream = 0;  // legacy default stream (the capture stream)
    cudaLaunchAttribute attr;
    attr.id = cudaLaunchAttributeProgrammaticStreamSerialization;
    attr.val.programmaticStreamSerializationAllowed = 1;
    cfg.attrs = &attr;
    cfg.numAttrs = 1;
    cudaLaunchKernelEx(&cfg, final_B_kernel, out);
}

// round 10
// speedup vs baseline: 1.3205x; 1.0985x over previous
#include <cuda_runtime.h>

#define MB 32
#define NP 256
#define QP (NP / 2)
#define ND 512

// scratch (no allocations allowed)
__device__ float g_D[MB * MB];      // D(i,j) = mean_p min_q d2
__device__ float g_phat[MB * MB];   // softmax(inner_dot) rows, precomputed

// ---- packed f32x2 helpers (Blackwell FFMA2 path) ---------------------------
__device__ __forceinline__ unsigned long long pack2(float lo, float hi) {
    unsigned long long r;
    asm("mov.b64 %0, {%1, %2};" : "=l"(r) : "f"(lo), "f"(hi));
    return r;
}
__device__ __forceinline__ unsigned long long fma2(unsigned long long a,
                                                   unsigned long long b,
                                                   unsigned long long c) {
    unsigned long long d;
    asm("fma.rn.f32x2 %0, %1, %2, %3;" : "=l"(d) : "l"(a), "l"(b), "l"(c));
    return d;
}
__device__ __forceinline__ void unpack2(unsigned long long v, float& lo, float& hi) {
    asm("mov.b64 {%0, %1}, %2;" : "=f"(lo), "=f"(hi) : "l"(v));
}

// ---------------------------------------------------------------------------
// Kernel A, flat grid of 1056 blocks x 128 threads:
//   blocks [0,1024): chamfer D(i,j) for ordered pair (i = b>>5, j = b&31)
//   blocks [1024,1056): inner_dot row i + its softmax -> g_phat row
// ---------------------------------------------------------------------------
__global__ void fused_A_kernel(const float* __restrict__ xyz,
                               const float* __restrict__ emb) {
    const int b = blockIdx.x;
    const int t = threadIdx.x;          // 0..127
    const int w = t >> 5, lane = t & 31;

    if (b < MB * MB) {
        // ---------------- chamfer part ----------------
        const int i = b >> 5, j = b & 31;
        __shared__ float4 s_j[2 * QP];
        __shared__ float  s_red[4];

        const float* shapes = xyz + MB * NP * 3;

        // stage shape j pair-interleaved SoA: {x0,x1,y0,y1} | {z0,z1,w0,w1}
        for (int q = t; q < NP; q += 128) {
            const float* p = shapes + (j * NP + q) * 3;
            float x = p[0], y = p[1], z = p[2];
            float ww = x * x + y * y + z * z;
            float* base = reinterpret_cast<float*>(&s_j[(q >> 1) * 2]);
            int s = q & 1;
            base[0 + s] = x;
            base[2 + s] = y;
            base[4 + s] = z;
            base[6 + s] = ww;
        }

        // my 2 a-points, pre-scaled by -2, splatted to f32x2
        unsigned long long a2x[2], a2y[2], a2z[2];
        float aw[2];
#pragma unroll
        for (int k = 0; k < 2; k++) {
            const float* p = shapes + (i * NP + t + 128 * k) * 3;
            float x = p[0], y = p[1], z = p[2];
            aw[k] = x * x + y * y + z * z;
            a2x[k] = pack2(-2.f * x, -2.f * x);
            a2y[k] = pack2(-2.f * y, -2.f * y);
            a2z[k] = pack2(-2.f * z, -2.f * z);
        }

        __syncthreads();

        const float INF = 3.4e38f;
        float mlo[2] = {INF, INF};
        float mhi[2] = {INF, INF};

        const ulonglong2* sj64 = reinterpret_cast<const ulonglong2*>(s_j);

#pragma unroll 4
        for (int qp = 0; qp < QP; qp++) {
            ulonglong2 xy = sj64[2 * qp + 0];  // {x01, y01}
            ulonglong2 zw = sj64[2 * qp + 1];  // {z01, w01}
#pragma unroll
            for (int k = 0; k < 2; k++) {
                unsigned long long s =
                    fma2(a2x[k], xy.x, fma2(a2y[k], xy.y, fma2(a2z[k], zw.x, zw.y)));
                float lo, hi;
                unpack2(s, lo, hi);
                mlo[k] = fminf(mlo[k], lo);
                mhi[k] = fminf(mhi[k], hi);
            }
        }

        float s = fminf(mlo[0], mhi[0]) + aw[0] + fminf(mlo[1], mhi[1]) + aw[1];
#pragma unroll
        for (int o = 16; o > 0; o >>= 1) s += __shfl_down_sync(0xffffffffu, s, o);
        if (lane == 0) s_red[w] = s;
        __syncthreads();
        if (t == 0)
            g_D[i * MB + j] = (s_red[0] + s_red[1] + s_red[2] + s_red[3]) * (1.f / NP);
    } else {
        // ---------------- inner_dot row + p_hat softmax ----------------
        const int i = b - MB * MB;
        __shared__ float s_dot[MB];

        // keep my slice of emb row i in registers, reuse for all j
        float eir[16];
        float ni = 0.f;
#pragma unroll
        for (int u = 0; u < 16; u++) {
            float e = emb[i * ND + u * 32 + lane];
            eir[u] = e;
            ni += e * e;
        }
#pragma unroll
        for (int o = 16; o > 0; o >>= 1) ni += __shfl_xor_sync(0xffffffffu, ni, o);
        const float inv_ni = rsqrtf(ni);

        for (int j = w; j < MB; j += 4) {
            const float* ej = emb + (MB + j) * ND;
            float dot = 0.f, nj = 0.f;
#pragma unroll
            for (int u = 0; u < 16; u++) {
                float e = ej[u * 32 + lane];
                dot += e * eir[u];
                nj += e * e;
            }
#pragma unroll
            for (int o = 16; o > 0; o >>= 1) {
                dot += __shfl_down_sync(0xffffffffu, dot, o);
                nj  += __shfl_down_sync(0xffffffffu, nj, o);
            }
            if (lane == 0) s_dot[j] = dot * rsqrtf(nj) * inv_ni;
        }
        __syncthreads();

        // warp 0: softmax over the 32 dots -> p_hat row
        if (w == 0) {
            float idot = s_dot[lane];
            float m = idot;
#pragma unroll
            for (int o = 16; o > 0; o >>= 1) m = fmaxf(m, __shfl_xor_sync(0xffffffffu, m, o));
            float e = expf(idot - m);
            float sum = e;
#pragma unroll
            for (int o = 16; o > 0; o >>= 1) sum += __shfl_xor_sync(0xffffffffu, sum, o);
            g_phat[i * MB + lane] = e / sum;
        }
    }
}

// ---------------------------------------------------------------------------
// Kernel B: 1 block x 1024 threads, PDL-launched. Warp i handles row i:
// cd softmax -> p; |p_hat - p| row sum. Warp 0 does the final sum.
// ---------------------------------------------------------------------------
__global__ void final_B_kernel(float* __restrict__ out) {
    cudaGridDependencySynchronize();

    __shared__ float s_row[MB];
    const int i = threadIdx.x >> 5, lane = threadIdx.x & 31;

    {
        float p_hat = g_phat[i * MB + lane];

        const float SIG = 1.0f * 0.997f / 3.0f;
        const float INV2S2 = 1.0f / (2.0f * SIG * SIG);
        float cd = g_D[i * MB + lane] + g_D[lane * MB + i];
        float nd = -(cd * cd) * INV2S2;
        float m2 = nd;
#pragma unroll
        for (int o = 16; o > 0; o >>= 1) m2 = fmaxf(m2, __shfl_xor_sync(0xffffffffu, m2, o));
        float e2 = expf(nd - m2);
        float sum2 = e2;
#pragma unroll
        for (int o = 16; o > 0; o >>= 1) sum2 += __shfl_xor_sync(0xffffffffu, sum2, o);
        float p = e2 / sum2;

        float diff = fabsf(p_hat - p);
#pragma unroll
        for (int o = 16; o > 0; o >>= 1) diff += __shfl_xor_sync(0xffffffffu, diff, o);
        if (lane == 0) s_row[i] = diff;
    }
    __syncthreads();

    if (i == 0) {
        float v = s_row[lane];
#pragma unroll
        for (int o = 16; o > 0; o >>= 1) v += __shfl_down_sync(0xffffffffu, v, o);
        if (lane == 0) out[0] = v * (1.0f / (MB * MB));
    }
}

extern "C" void kernel_launch(void* const* d_in, const int* in_sizes, int n_in,
                              void* d_out, int out_size) {
    const float* embeddings = (const float*)d_in[0];  // (64, 512) fp32
    const float* xyz        = (const float*)d_in[1];  // (64, 256, 3) fp32
    float* out = (float*)d_out;

    fused_A_kernel<<<MB * MB + MB, 128>>>(xyz, embeddings);

    // PDL launch of the epilogue: overlaps its launch latency with A's tail.
    cudaLaunchConfig_t cfg = {};
    cfg.gridDim  = dim3(1, 1, 1);
    cfg.blockDim = dim3(MB * 32, 1, 1);
    cfg.dynamicSmemBytes = 0;
    cfg.stream = 0;
    cudaLaunchAttribute attr;
    attr.id = cudaLaunchAttributeProgrammaticStreamSerialization;
    attr.val.programmaticStreamSerializationAllowed = 1;
    cfg.attrs = &attr;
    cfg.numAttrs = 1;
    cudaLaunchKernelEx(&cfg, final_B_kernel, out);
}